// round 1
// baseline (speedup 1.0000x reference)
#include <cuda_runtime.h>
#include <cstdint>

// ---------------------------------------------------------------------------
// DummyTeModel: 6 chained GEMMs, all of form C[M,N] = A[M,K] @ W[N,K]^T + b[N]
//   1) x[16384,2048]   @ w1[4096,2048]^T  -> buf1 [16384,4096]
//   2) buf1            @ w2[2048,4096]^T  -> buf2 [16384,2048]
//   3) per layer (x2): grouped G=4:
//        g1: buf2(g)[4096,2048] @ g1w(g)[4096,2048]^T -> buf1(g)[4096,4096]
//        g2: buf1(g)[4096,4096] @ g2w(g)[2048,4096]^T -> buf2(g)/out
// fp32 throughout (6-deep chain makes bf16/tf32 fail rel_err<1e-3).
// Uses packed fma.rn.f32x2 (sm_100+) for 2x fp32 FMA throughput.
// ---------------------------------------------------------------------------

#define BM 128
#define BN 128
#define BK 16
#define PAD 4   // row stride BM+PAD = 132 floats = 528B, keeps 16B alignment

static const int T_TOK = 16384;   // B*S = 4*4096
static const int HID   = 2048;
static const int IMM   = 4096;    // 2*H
static const int NGRP  = 4;

// scratch (allocation-guard-safe __device__ globals)
__device__ float g_buf1[(size_t)16384 * 4096];  // 256 MB
__device__ float g_buf2[(size_t)16384 * 2048];  // 128 MB

__device__ __forceinline__ unsigned long long pack2(float lo, float hi) {
    unsigned long long r;
    asm("mov.b64 %0, {%1, %2};" : "=l"(r) : "f"(lo), "f"(hi));
    return r;
}
__device__ __forceinline__ unsigned long long fma2(unsigned long long a,
                                                   unsigned long long b,
                                                   unsigned long long c) {
    unsigned long long d;
    asm("fma.rn.f32x2 %0, %1, %2, %3;" : "=l"(d) : "l"(a), "l"(b), "l"(c));
    return d;
}
__device__ __forceinline__ void unpack2(unsigned long long v, float& lo, float& hi) {
    asm("mov.b64 {%0, %1}, %2;" : "=f"(lo), "=f"(hi) : "l"(v));
}

// C = A @ W^T + bias. A:[M,K] row-major, W:[N,K] row-major, C:[M,N].
// Grouped via blockIdx.z: per-group contiguous slabs of A, W, bias, C.
// Requires: M,N % 128 == 0, K % 16 == 0 (all shapes here satisfy this).
__global__ __launch_bounds__(256, 2)
void gemm_tn_f32(const float* __restrict__ A, const float* __restrict__ W,
                 const float* __restrict__ bias, float* __restrict__ C,
                 int M, int N, int K)
{
    const long g = blockIdx.z;
    A    += g * (long)M * K;
    W    += g * (long)N * K;
    bias += g * (long)N;
    C    += g * (long)M * N;

    __shared__ float As[BK][BM + PAD];
    __shared__ float Ws[BK][BN + PAD];

    const int tid = threadIdx.x;
    const int tx  = tid & 15;    // 0..15 -> n
    const int ty  = tid >> 4;    // 0..15 -> m

    const int m0 = blockIdx.y * BM;
    const int n0 = blockIdx.x * BN;

    const float* Aptr = A + (long)m0 * K;
    const float* Wptr = W + (long)n0 * K;

    unsigned long long acc[8][4];
    #pragma unroll
    for (int i = 0; i < 8; i++)
        #pragma unroll
        for (int j = 0; j < 4; j++) acc[i][j] = 0ULL;

    for (int k0 = 0; k0 < K; k0 += BK) {
        // --- load A tile (128 rows x 16 k) : 512 float4s, 2 per thread ---
        #pragma unroll
        for (int i = 0; i < 2; i++) {
            int l  = tid + i * 256;
            int r  = l >> 2;
            int c4 = (l & 3) * 4;
            float4 v = *(const float4*)(Aptr + (long)r * K + k0 + c4);
            As[c4 + 0][r] = v.x; As[c4 + 1][r] = v.y;
            As[c4 + 2][r] = v.z; As[c4 + 3][r] = v.w;
        }
        // --- load W tile (128 rows x 16 k) ---
        #pragma unroll
        for (int i = 0; i < 2; i++) {
            int l  = tid + i * 256;
            int r  = l >> 2;
            int c4 = (l & 3) * 4;
            float4 v = *(const float4*)(Wptr + (long)r * K + k0 + c4);
            Ws[c4 + 0][r] = v.x; Ws[c4 + 1][r] = v.y;
            Ws[c4 + 2][r] = v.z; Ws[c4 + 3][r] = v.w;
        }
        __syncthreads();

        #pragma unroll
        for (int kk = 0; kk < BK; kk++) {
            // split fragments (x*4 and 64+x*4): conflict-free LDS.128
            float4 a0 = *(const float4*)&As[kk][ty * 4];
            float4 a1 = *(const float4*)&As[kk][64 + ty * 4];
            float4 b0 = *(const float4*)&Ws[kk][tx * 4];
            float4 b1 = *(const float4*)&Ws[kk][64 + tx * 4];

            unsigned long long bp[4];
            bp[0] = pack2(b0.x, b0.y);
            bp[1] = pack2(b0.z, b0.w);
            bp[2] = pack2(b1.x, b1.y);
            bp[3] = pack2(b1.z, b1.w);

            float av[8] = {a0.x, a0.y, a0.z, a0.w, a1.x, a1.y, a1.z, a1.w};
            #pragma unroll
            for (int i = 0; i < 8; i++) {
                unsigned long long ad = pack2(av[i], av[i]);
                #pragma unroll
                for (int j = 0; j < 4; j++)
                    acc[i][j] = fma2(ad, bp[j], acc[i][j]);
            }
        }
        __syncthreads();
    }

    // --- epilogue: bias + store (coalesced float4) ---
    float bv[8];
    #pragma unroll
    for (int j = 0; j < 4; j++) {
        bv[j]     = bias[n0 + tx * 4 + j];
        bv[4 + j] = bias[n0 + 64 + tx * 4 + j];
    }
    #pragma unroll
    for (int i = 0; i < 8; i++) {
        int m = m0 + ((i < 4) ? (ty * 4 + i) : (64 + ty * 4 + (i - 4)));
        float o[8];
        unpack2(acc[i][0], o[0], o[1]);
        unpack2(acc[i][1], o[2], o[3]);
        unpack2(acc[i][2], o[4], o[5]);
        unpack2(acc[i][3], o[6], o[7]);
        float4 lo = make_float4(o[0] + bv[0], o[1] + bv[1], o[2] + bv[2], o[3] + bv[3]);
        float4 hi = make_float4(o[4] + bv[4], o[5] + bv[5], o[6] + bv[6], o[7] + bv[7]);
        float* cp = C + (long)m * N + n0;
        *(float4*)(cp + tx * 4)      = lo;
        *(float4*)(cp + 64 + tx * 4) = hi;
    }
}

extern "C" void kernel_launch(void* const* d_in, const int* in_sizes, int n_in,
                              void* d_out, int out_size)
{
    (void)in_sizes; (void)n_in; (void)out_size;
    const float* x  = (const float*)d_in[0];
    const float* w1 = (const float*)d_in[1];
    const float* b1 = (const float*)d_in[2];
    const float* w2 = (const float*)d_in[3];
    const float* b2 = (const float*)d_in[4];
    const float* g1w[2] = { (const float*)d_in[5],  (const float*)d_in[9]  };
    const float* g1b[2] = { (const float*)d_in[6],  (const float*)d_in[10] };
    const float* g2w[2] = { (const float*)d_in[7],  (const float*)d_in[11] };
    const float* g2b[2] = { (const float*)d_in[8],  (const float*)d_in[12] };
    float* out = (float*)d_out;

    float *buf1 = nullptr, *buf2 = nullptr;
    cudaGetSymbolAddress((void**)&buf1, g_buf1);
    cudaGetSymbolAddress((void**)&buf2, g_buf2);

    const int Mg = T_TOK / NGRP;   // 4096 rows per group
    dim3 blk(256);

    // 1) dense: x @ w1^T -> buf1 [T, 4096]
    gemm_tn_f32<<<dim3(IMM / BN, T_TOK / BM, 1), blk>>>(x, w1, b1, buf1, T_TOK, IMM, HID);
    // 2) dense: buf1 @ w2^T -> buf2 [T, 2048]
    gemm_tn_f32<<<dim3(HID / BN, T_TOK / BM, 1), blk>>>(buf1, w2, b2, buf2, T_TOK, HID, IMM);
    // 3..6) two grouped-MLP layers
    for (int li = 0; li < 2; li++) {
        gemm_tn_f32<<<dim3(IMM / BN, Mg / BM, NGRP), blk>>>(buf2, g1w[li], g1b[li], buf1,
                                                            Mg, IMM, HID);
        float* dst = (li == 1) ? out : buf2;
        gemm_tn_f32<<<dim3(HID / BN, Mg / BM, NGRP), blk>>>(buf1, g2w[li], g2b[li], dst,
                                                            Mg, HID, IMM);
    }
}

// round 7
// speedup vs baseline: 2.1359x; 2.1359x over previous
#include <cuda_runtime.h>
#include <cuda_bf16.h>
#include <cstdint>

// ---------------------------------------------------------------------------
// 6 chained GEMMs C = A @ W^T + b via split-bf16 (3-pass) mma.sync HMMA:
//   A = Ah + Al (bf16), W = Wh + Wl (bf16)
//   C ~= Ah*Wh + Ah*Wl + Al*Wh   (fp32 register accumulation)
// R5 fix: B operand (W, stored [N,K] K-major) must use NON-trans ldmatrix —
// mma row.col's B is k-contiguous col-major, identical to [N,K] row-major.
// CTA tile 128x256, 8 warps of 64x64, BK=32, 2-stage cp.async double buffer.
// ---------------------------------------------------------------------------

#define BM 128
#define BN 256
#define BKC 32
#define ROWB 80u            // padded smem row stride (32 bf16 = 64B + 16B pad)
#define STG_A   10240u      // 128 rows * 80B
#define STG_W   20480u      // 256 rows * 80B
#define STG_BYTES 61440u    // Ah + Al + Wh + Wl
#define SMEM_SZ (2u * STG_BYTES)

static const int T_TOK = 16384, HID = 2048, IMM = 4096;

// ---- scratch (__device__ globals; allocation-guard-safe) ----
__device__ __nv_bfloat16 g_whi[150994944];
__device__ __nv_bfloat16 g_wlo[150994944];
__device__ __nv_bfloat16 g_aAhi[67108864];   // 16384 x 4096
__device__ __nv_bfloat16 g_aAlo[67108864];
__device__ __nv_bfloat16 g_aBhi[33554432];   // 16384 x 2048
__device__ __nv_bfloat16 g_aBlo[33554432];

__device__ __forceinline__ uint32_t smem_u32(const void* p) {
    uint32_t a;
    asm("{ .reg .u64 t; cvta.to.shared.u64 t, %1; cvt.u32.u64 %0, t; }" : "=r"(a) : "l"(p));
    return a;
}
__device__ __forceinline__ void cp16(uint32_t dst, const void* src) {
    asm volatile("cp.async.cg.shared.global [%0], [%1], 16;" :: "r"(dst), "l"(src));
}
__device__ __forceinline__ void cp_commit() {
    asm volatile("cp.async.commit_group;" ::: "memory");
}
__device__ __forceinline__ void cp_wait1() {
    asm volatile("cp.async.wait_group 1;" ::: "memory");
}
__device__ __forceinline__ void ldsm4(uint32_t* r, uint32_t a) {
    asm volatile("ldmatrix.sync.aligned.m8n8.x4.shared.b16 {%0,%1,%2,%3}, [%4];"
                 : "=r"(r[0]), "=r"(r[1]), "=r"(r[2]), "=r"(r[3]) : "r"(a));
}
__device__ __forceinline__ void mma16816(float* d, const uint32_t* a, const uint32_t* b) {
    asm volatile("mma.sync.aligned.m16n8k16.row.col.f32.bf16.bf16.f32 "
                 "{%0,%1,%2,%3}, {%4,%5,%6,%7}, {%8,%9}, {%0,%1,%2,%3};"
                 : "+f"(d[0]), "+f"(d[1]), "+f"(d[2]), "+f"(d[3])
                 : "r"(a[0]), "r"(a[1]), "r"(a[2]), "r"(a[3]), "r"(b[0]), "r"(b[1]));
}

// ---- fp32 -> (bf16 hi, bf16 lo) split ----
__global__ void conv_split(const float4* __restrict__ in,
                           __nv_bfloat16* __restrict__ hi,
                           __nv_bfloat16* __restrict__ lo, int n4)
{
    int i = blockIdx.x * blockDim.x + threadIdx.x;
    if (i >= n4) return;
    float4 v = in[i];
    __nv_bfloat16 h0 = __float2bfloat16(v.x), h1 = __float2bfloat16(v.y);
    __nv_bfloat16 h2 = __float2bfloat16(v.z), h3 = __float2bfloat16(v.w);
    __nv_bfloat16 l0 = __float2bfloat16(v.x - __bfloat162float(h0));
    __nv_bfloat16 l1 = __float2bfloat16(v.y - __bfloat162float(h1));
    __nv_bfloat16 l2 = __float2bfloat16(v.z - __bfloat162float(h2));
    __nv_bfloat16 l3 = __float2bfloat16(v.w - __bfloat162float(h3));
    uint2 hp, lp;
    hp.x = (uint32_t)__bfloat16_as_ushort(h0) | ((uint32_t)__bfloat16_as_ushort(h1) << 16);
    hp.y = (uint32_t)__bfloat16_as_ushort(h2) | ((uint32_t)__bfloat16_as_ushort(h3) << 16);
    lp.x = (uint32_t)__bfloat16_as_ushort(l0) | ((uint32_t)__bfloat16_as_ushort(l1) << 16);
    lp.y = (uint32_t)__bfloat16_as_ushort(l2) | ((uint32_t)__bfloat16_as_ushort(l3) << 16);
    ((uint2*)hi)[i] = hp;
    ((uint2*)lo)[i] = lp;
}

__device__ __forceinline__ void split_store(__nv_bfloat16* __restrict__ hi,
                                            __nv_bfloat16* __restrict__ lo,
                                            size_t off, float y0, float y1)
{
    __nv_bfloat16 h0 = __float2bfloat16(y0), h1 = __float2bfloat16(y1);
    __nv_bfloat16 l0 = __float2bfloat16(y0 - __bfloat162float(h0));
    __nv_bfloat16 l1 = __float2bfloat16(y1 - __bfloat162float(h1));
    *(uint32_t*)(hi + off) =
        (uint32_t)__bfloat16_as_ushort(h0) | ((uint32_t)__bfloat16_as_ushort(h1) << 16);
    *(uint32_t*)(lo + off) =
        (uint32_t)__bfloat16_as_ushort(l0) | ((uint32_t)__bfloat16_as_ushort(l1) << 16);
}

// C[M,N] = (Ah+Al)[M,K] @ (Wh+Wl)[N,K]^T + bias; grouped via blockIdx.z.
__global__ void __launch_bounds__(256, 1)
gemm3x(const __nv_bfloat16* __restrict__ Ah, const __nv_bfloat16* __restrict__ Al,
       const __nv_bfloat16* __restrict__ Wh, const __nv_bfloat16* __restrict__ Wl,
       const float* __restrict__ bias, float* __restrict__ Cf,
       __nv_bfloat16* __restrict__ Chi, __nv_bfloat16* __restrict__ Clo,
       int M, int N, int K, int wantF32)
{
    extern __shared__ char smem[];
    const uint32_t sb = smem_u32(smem);

    const int tid  = threadIdx.x;
    const int lane = tid & 31;
    const int warp = tid >> 5;
    const int wm   = warp >> 2;   // 0..1
    const int wn   = warp & 3;    // 0..3
    const size_t g = blockIdx.z;
    const int n0 = blockIdx.x * BN;
    const int m0 = blockIdx.y * BM;

    const __nv_bfloat16* Agh = Ah + g * (size_t)M * K + (size_t)m0 * K;
    const __nv_bfloat16* Agl = Al + g * (size_t)M * K + (size_t)m0 * K;
    const __nv_bfloat16* Wgh = Wh + g * (size_t)N * K + (size_t)n0 * K;
    const __nv_bfloat16* Wgl = Wl + g * (size_t)N * K + (size_t)n0 * K;

    // issue one stage (12 x 16B cp.async per thread)
    auto load_stage = [&](int c, int s) {
        const uint32_t st = sb + (uint32_t)s * STG_BYTES;
        const size_t kof = (size_t)c * BKC;
        #pragma unroll
        for (int i = 0; i < 12; i++) {
            int l = i * 256 + tid;
            const __nv_bfloat16* src;
            uint32_t base;
            int t;
            if (i < 2)      { t = l;        src = Agh; base = st; }
            else if (i < 4) { t = l - 512;  src = Agl; base = st + STG_A; }
            else if (i < 8) { t = l - 1024; src = Wgh; base = st + 2 * STG_A; }
            else            { t = l - 2048; src = Wgl; base = st + 2 * STG_A + STG_W; }
            int row = t >> 2, cc = t & 3;
            cp16(base + (uint32_t)row * ROWB + (uint32_t)cc * 16,
                 src + (size_t)row * K + kof + cc * 8);
        }
        cp_commit();
    };

    float acc[4][8][4];
    #pragma unroll
    for (int mf = 0; mf < 4; mf++)
        #pragma unroll
        for (int nf = 0; nf < 8; nf++)
            #pragma unroll
            for (int q = 0; q < 4; q++) acc[mf][nf][q] = 0.f;

    const int KC = K / BKC;
    load_stage(0, 0);
    load_stage(1, 1);

    // ldmatrix base addresses (non-trans for BOTH operands; K-major tiles)
    const uint32_t aRow = (uint32_t)(wm * 64 + (lane & 15)) * ROWB + (uint32_t)(lane >> 4) * 16;
    const uint32_t bRow = (uint32_t)(wn * 64 + ((lane >> 4) << 3) + (lane & 7)) * ROWB
                        + (uint32_t)((lane >> 3) & 1) * 16;

    for (int c = 0; c < KC; c++) {
        const int s = c & 1;
        const uint32_t st = sb + (uint32_t)s * STG_BYTES;
        cp_wait1();
        __syncthreads();

        uint32_t a[4][4], bh[4][4], bl[4][4];
        #pragma unroll
        for (int ks = 0; ks < 2; ks++) {
            const uint32_t ko = (uint32_t)ks * 32;  // 16 bf16 = 32B
            // Ah fragments (m64 x k16)
            #pragma unroll
            for (int mf = 0; mf < 4; mf++)
                ldsm4(a[mf], st + aRow + (uint32_t)mf * 16 * ROWB + ko);
            // Wh fragments (n64 x k16) — NON-trans (K-major == mma col layout)
            #pragma unroll
            for (int nf2 = 0; nf2 < 4; nf2++)
                ldsm4(bh[nf2], st + 2 * STG_A + bRow + (uint32_t)nf2 * 16 * ROWB + ko);
            #pragma unroll
            for (int mf = 0; mf < 4; mf++)
                #pragma unroll
                for (int nf2 = 0; nf2 < 4; nf2++) {
                    mma16816(acc[mf][2 * nf2],     a[mf], &bh[nf2][0]);
                    mma16816(acc[mf][2 * nf2 + 1], a[mf], &bh[nf2][2]);
                }
            // Wl fragments
            #pragma unroll
            for (int nf2 = 0; nf2 < 4; nf2++)
                ldsm4(bl[nf2], st + 2 * STG_A + STG_W + bRow + (uint32_t)nf2 * 16 * ROWB + ko);
            #pragma unroll
            for (int mf = 0; mf < 4; mf++)
                #pragma unroll
                for (int nf2 = 0; nf2 < 4; nf2++) {
                    mma16816(acc[mf][2 * nf2],     a[mf], &bl[nf2][0]);
                    mma16816(acc[mf][2 * nf2 + 1], a[mf], &bl[nf2][2]);
                }
            // Al fragments, reuse Wh
            #pragma unroll
            for (int mf = 0; mf < 4; mf++)
                ldsm4(a[mf], st + STG_A + aRow + (uint32_t)mf * 16 * ROWB + ko);
            #pragma unroll
            for (int mf = 0; mf < 4; mf++)
                #pragma unroll
                for (int nf2 = 0; nf2 < 4; nf2++) {
                    mma16816(acc[mf][2 * nf2],     a[mf], &bh[nf2][0]);
                    mma16816(acc[mf][2 * nf2 + 1], a[mf], &bh[nf2][2]);
                }
        }
        __syncthreads();
        if (c + 2 < KC) load_stage(c + 2, s);
        else cp_commit();   // keep group-count invariant for cp_wait1
    }

    // ---- epilogue ----
    const size_t co = g * (size_t)M * N;
    const float* bp = bias + g * N;
    #pragma unroll
    for (int mf = 0; mf < 4; mf++) {
        const int r0 = m0 + wm * 64 + mf * 16 + (lane >> 2);
        #pragma unroll
        for (int nf = 0; nf < 8; nf++) {
            const int cb = n0 + wn * 64 + nf * 8 + (lane & 3) * 2;
            const float b0 = bp[cb], b1 = bp[cb + 1];
            const float y00 = acc[mf][nf][0] + b0, y01 = acc[mf][nf][1] + b1;
            const float y10 = acc[mf][nf][2] + b0, y11 = acc[mf][nf][3] + b1;
            const size_t o0 = co + (size_t)r0 * N + cb;
            const size_t o1 = co + (size_t)(r0 + 8) * N + cb;
            if (wantF32) {
                *(float2*)(Cf + o0) = make_float2(y00, y01);
                *(float2*)(Cf + o1) = make_float2(y10, y11);
            } else {
                split_store(Chi, Clo, o0, y00, y01);
                split_store(Chi, Clo, o1, y10, y11);
            }
        }
    }
}

// ---------------------------------------------------------------------------
extern "C" void kernel_launch(void* const* d_in, const int* in_sizes, int n_in,
                              void* d_out, int out_size)
{
    (void)in_sizes; (void)n_in; (void)out_size;
    const float* x  = (const float*)d_in[0];
    const float* w1 = (const float*)d_in[1];
    const float* b1 = (const float*)d_in[2];
    const float* w2 = (const float*)d_in[3];
    const float* b2 = (const float*)d_in[4];
    const float* g1w[2] = { (const float*)d_in[5],  (const float*)d_in[9]  };
    const float* g1b[2] = { (const float*)d_in[6],  (const float*)d_in[10] };
    const float* g2w[2] = { (const float*)d_in[7],  (const float*)d_in[11] };
    const float* g2b[2] = { (const float*)d_in[8],  (const float*)d_in[12] };
    float* out = (float*)d_out;

    __nv_bfloat16 *whi, *wlo, *aAhi, *aAlo, *aBhi, *aBlo;
    cudaGetSymbolAddress((void**)&whi,  g_whi);
    cudaGetSymbolAddress((void**)&wlo,  g_wlo);
    cudaGetSymbolAddress((void**)&aAhi, g_aAhi);
    cudaGetSymbolAddress((void**)&aAlo, g_aAlo);
    cudaGetSymbolAddress((void**)&aBhi, g_aBhi);
    cudaGetSymbolAddress((void**)&aBlo, g_aBlo);

    const size_t OW1 = 0, OW2 = 8388608;
    const size_t OG[4] = { 16777216, 50331648, 83886080, 117440512 };

    cudaFuncSetAttribute(gemm3x, cudaFuncAttributeMaxDynamicSharedMemorySize, SMEM_SZ);

    auto conv = [&](const float* src, __nv_bfloat16* h, __nv_bfloat16* l, size_t n) {
        int n4 = (int)(n / 4);
        conv_split<<<(n4 + 255) / 256, 256>>>((const float4*)src, h, l, n4);
    };
    conv(x,      aBhi,        aBlo,        (size_t)T_TOK * HID);
    conv(w1,     whi + OW1,   wlo + OW1,   (size_t)IMM * HID);
    conv(w2,     whi + OW2,   wlo + OW2,   (size_t)HID * IMM);
    conv(g1w[0], whi + OG[0], wlo + OG[0], (size_t)4 * IMM * HID);
    conv(g2w[0], whi + OG[1], wlo + OG[1], (size_t)4 * HID * IMM);
    conv(g1w[1], whi + OG[2], wlo + OG[2], (size_t)4 * IMM * HID);
    conv(g2w[1], whi + OG[3], wlo + OG[3], (size_t)4 * HID * IMM);

    const int Mg = T_TOK / 4;
    dim3 blk(256);

    // 1) x @ w1^T -> actA  [16384, 4096]
    gemm3x<<<dim3(IMM / BN, T_TOK / BM, 1), blk, SMEM_SZ>>>(
        aBhi, aBlo, whi + OW1, wlo + OW1, b1, nullptr, aAhi, aAlo,
        T_TOK, IMM, HID, 0);
    // 2) actA @ w2^T -> actB  [16384, 2048]
    gemm3x<<<dim3(HID / BN, T_TOK / BM, 1), blk, SMEM_SZ>>>(
        aAhi, aAlo, whi + OW2, wlo + OW2, b2, nullptr, aBhi, aBlo,
        T_TOK, HID, IMM, 0);
    // 3..6) two grouped-MLP layers
    for (int li = 0; li < 2; li++) {
        gemm3x<<<dim3(IMM / BN, Mg / BM, 4), blk, SMEM_SZ>>>(
            aBhi, aBlo, whi + OG[2 * li], wlo + OG[2 * li], g1b[li],
            nullptr, aAhi, aAlo, Mg, IMM, HID, 0);
        int fin = (li == 1);
        gemm3x<<<dim3(HID / BN, Mg / BM, 4), blk, SMEM_SZ>>>(
            aAhi, aAlo, whi + OG[2 * li + 1], wlo + OG[2 * li + 1], g2b[li],
            fin ? out : nullptr, aBhi, aBlo, Mg, HID, IMM, fin);
    }
}

// round 8
// speedup vs baseline: 2.3609x; 1.1053x over previous
#include <cuda_runtime.h>
#include <cuda_bf16.h>
#include <cstdint>

// ---------------------------------------------------------------------------
// 6 chained GEMMs C = A @ W^T + b via split-bf16 (3-pass) mma.sync HMMA:
//   C ~= Ah*Wh + Ah*Wl + Al*Wh  (fp32 register accumulation)
// R8: occupancy fix. 64x64 warp tiles (128 acc regs, 1 CTA/SM) left the
// kernel latency-bound 4.7x over its smem floor. Now: CTA 128x128, 8 warps
// of 64x32 (64 acc regs, ~116 live), launch_bounds(256,2) -> 2 CTAs/SM,
// 4 warps/SMSP. Smem floor worsens 2.9->4.2ms but exposure multiplier drops.
// ---------------------------------------------------------------------------

#define BM 128
#define BN 128
#define BKC 32
#define ROWB 80u            // padded smem row stride (32 bf16 = 64B + 16B pad)
#define STG_T   10240u      // one 128x32 bf16 tile: 128 rows * 80B
#define STG_BYTES 40960u    // Ah + Al + Wh + Wl
#define SMEM_SZ (2u * STG_BYTES)

static const int T_TOK = 16384, HID = 2048, IMM = 4096;

// ---- scratch (__device__ globals; allocation-guard-safe) ----
__device__ __nv_bfloat16 g_whi[150994944];
__device__ __nv_bfloat16 g_wlo[150994944];
__device__ __nv_bfloat16 g_aAhi[67108864];   // 16384 x 4096
__device__ __nv_bfloat16 g_aAlo[67108864];
__device__ __nv_bfloat16 g_aBhi[33554432];   // 16384 x 2048
__device__ __nv_bfloat16 g_aBlo[33554432];

__device__ __forceinline__ uint32_t smem_u32(const void* p) {
    uint32_t a;
    asm("{ .reg .u64 t; cvta.to.shared.u64 t, %1; cvt.u32.u64 %0, t; }" : "=r"(a) : "l"(p));
    return a;
}
__device__ __forceinline__ void cp16(uint32_t dst, const void* src) {
    asm volatile("cp.async.cg.shared.global [%0], [%1], 16;" :: "r"(dst), "l"(src));
}
__device__ __forceinline__ void cp_commit() {
    asm volatile("cp.async.commit_group;" ::: "memory");
}
__device__ __forceinline__ void cp_wait1() {
    asm volatile("cp.async.wait_group 1;" ::: "memory");
}
__device__ __forceinline__ void ldsm4(uint32_t* r, uint32_t a) {
    asm volatile("ldmatrix.sync.aligned.m8n8.x4.shared.b16 {%0,%1,%2,%3}, [%4];"
                 : "=r"(r[0]), "=r"(r[1]), "=r"(r[2]), "=r"(r[3]) : "r"(a));
}
__device__ __forceinline__ void mma16816(float* d, const uint32_t* a, const uint32_t* b) {
    asm volatile("mma.sync.aligned.m16n8k16.row.col.f32.bf16.bf16.f32 "
                 "{%0,%1,%2,%3}, {%4,%5,%6,%7}, {%8,%9}, {%0,%1,%2,%3};"
                 : "+f"(d[0]), "+f"(d[1]), "+f"(d[2]), "+f"(d[3])
                 : "r"(a[0]), "r"(a[1]), "r"(a[2]), "r"(a[3]), "r"(b[0]), "r"(b[1]));
}

// ---- fp32 -> (bf16 hi, bf16 lo) split ----
__global__ void conv_split(const float4* __restrict__ in,
                           __nv_bfloat16* __restrict__ hi,
                           __nv_bfloat16* __restrict__ lo, int n4)
{
    int i = blockIdx.x * blockDim.x + threadIdx.x;
    if (i >= n4) return;
    float4 v = in[i];
    __nv_bfloat16 h0 = __float2bfloat16(v.x), h1 = __float2bfloat16(v.y);
    __nv_bfloat16 h2 = __float2bfloat16(v.z), h3 = __float2bfloat16(v.w);
    __nv_bfloat16 l0 = __float2bfloat16(v.x - __bfloat162float(h0));
    __nv_bfloat16 l1 = __float2bfloat16(v.y - __bfloat162float(h1));
    __nv_bfloat16 l2 = __float2bfloat16(v.z - __bfloat162float(h2));
    __nv_bfloat16 l3 = __float2bfloat16(v.w - __bfloat162float(h3));
    uint2 hp, lp;
    hp.x = (uint32_t)__bfloat16_as_ushort(h0) | ((uint32_t)__bfloat16_as_ushort(h1) << 16);
    hp.y = (uint32_t)__bfloat16_as_ushort(h2) | ((uint32_t)__bfloat16_as_ushort(h3) << 16);
    lp.x = (uint32_t)__bfloat16_as_ushort(l0) | ((uint32_t)__bfloat16_as_ushort(l1) << 16);
    lp.y = (uint32_t)__bfloat16_as_ushort(l2) | ((uint32_t)__bfloat16_as_ushort(l3) << 16);
    ((uint2*)hi)[i] = hp;
    ((uint2*)lo)[i] = lp;
}

__device__ __forceinline__ void split_store(__nv_bfloat16* __restrict__ hi,
                                            __nv_bfloat16* __restrict__ lo,
                                            size_t off, float y0, float y1)
{
    __nv_bfloat16 h0 = __float2bfloat16(y0), h1 = __float2bfloat16(y1);
    __nv_bfloat16 l0 = __float2bfloat16(y0 - __bfloat162float(h0));
    __nv_bfloat16 l1 = __float2bfloat16(y1 - __bfloat162float(h1));
    *(uint32_t*)(hi + off) =
        (uint32_t)__bfloat16_as_ushort(h0) | ((uint32_t)__bfloat16_as_ushort(h1) << 16);
    *(uint32_t*)(lo + off) =
        (uint32_t)__bfloat16_as_ushort(l0) | ((uint32_t)__bfloat16_as_ushort(l1) << 16);
}

// C[M,N] = (Ah+Al)[M,K] @ (Wh+Wl)[N,K]^T + bias; grouped via blockIdx.z.
__global__ void __launch_bounds__(256, 2)
gemm3x(const __nv_bfloat16* __restrict__ Ah, const __nv_bfloat16* __restrict__ Al,
       const __nv_bfloat16* __restrict__ Wh, const __nv_bfloat16* __restrict__ Wl,
       const float* __restrict__ bias, float* __restrict__ Cf,
       __nv_bfloat16* __restrict__ Chi, __nv_bfloat16* __restrict__ Clo,
       int M, int N, int K, int wantF32)
{
    extern __shared__ char smem[];
    const uint32_t sb = smem_u32(smem);

    const int tid  = threadIdx.x;
    const int lane = tid & 31;
    const int warp = tid >> 5;
    const int wm   = warp >> 2;   // 0..1 -> m offset 64
    const int wn   = warp & 3;    // 0..3 -> n offset 32
    const size_t g = blockIdx.z;
    const int n0 = blockIdx.x * BN;
    const int m0 = blockIdx.y * BM;

    const __nv_bfloat16* Agh = Ah + g * (size_t)M * K + (size_t)m0 * K;
    const __nv_bfloat16* Agl = Al + g * (size_t)M * K + (size_t)m0 * K;
    const __nv_bfloat16* Wgh = Wh + g * (size_t)N * K + (size_t)n0 * K;
    const __nv_bfloat16* Wgl = Wl + g * (size_t)N * K + (size_t)n0 * K;

    // one stage = 4 tiles x 512 x 16B = 2048 cp16; 8 per thread
    auto load_stage = [&](int c, int s) {
        const uint32_t st = sb + (uint32_t)s * STG_BYTES;
        const size_t kof = (size_t)c * BKC;
        #pragma unroll
        for (int i = 0; i < 8; i++) {
            int l = i * 256 + tid;
            const __nv_bfloat16* src;
            uint32_t base;
            int t;
            if (i < 2)      { t = l;        src = Agh; base = st; }
            else if (i < 4) { t = l - 512;  src = Agl; base = st + STG_T; }
            else if (i < 6) { t = l - 1024; src = Wgh; base = st + 2 * STG_T; }
            else            { t = l - 1536; src = Wgl; base = st + 3 * STG_T; }
            int row = t >> 2, cc = t & 3;
            cp16(base + (uint32_t)row * ROWB + (uint32_t)cc * 16,
                 src + (size_t)row * K + kof + cc * 8);
        }
        cp_commit();
    };

    float acc[4][4][4];
    #pragma unroll
    for (int mf = 0; mf < 4; mf++)
        #pragma unroll
        for (int nf = 0; nf < 4; nf++)
            #pragma unroll
            for (int q = 0; q < 4; q++) acc[mf][nf][q] = 0.f;

    const int KC = K / BKC;
    load_stage(0, 0);
    load_stage(1, 1);

    // ldmatrix base addresses (non-trans; both operands K-major)
    const uint32_t aRow = (uint32_t)(wm * 64 + (lane & 15)) * ROWB + (uint32_t)(lane >> 4) * 16;
    const uint32_t bRow = (uint32_t)(wn * 32 + ((lane >> 4) << 3) + (lane & 7)) * ROWB
                        + (uint32_t)((lane >> 3) & 1) * 16;

    for (int c = 0; c < KC; c++) {
        const int s = c & 1;
        const uint32_t st = sb + (uint32_t)s * STG_BYTES;
        cp_wait1();
        __syncthreads();

        #pragma unroll
        for (int ks = 0; ks < 2; ks++) {
            const uint32_t ko = (uint32_t)ks * 32;  // 16 bf16 = 32B
            uint32_t a[4][4], bh[2][4], bl[2][4];
            // Ah (m64 x k16) + Wh/Wl (n32 x k16 each)
            #pragma unroll
            for (int mf = 0; mf < 4; mf++)
                ldsm4(a[mf], st + aRow + (uint32_t)mf * 16 * ROWB + ko);
            #pragma unroll
            for (int nf2 = 0; nf2 < 2; nf2++)
                ldsm4(bh[nf2], st + 2 * STG_T + bRow + (uint32_t)nf2 * 16 * ROWB + ko);
            #pragma unroll
            for (int nf2 = 0; nf2 < 2; nf2++)
                ldsm4(bl[nf2], st + 3 * STG_T + bRow + (uint32_t)nf2 * 16 * ROWB + ko);
            // pass 1: Ah * Wh
            #pragma unroll
            for (int mf = 0; mf < 4; mf++)
                #pragma unroll
                for (int nf2 = 0; nf2 < 2; nf2++) {
                    mma16816(acc[mf][2 * nf2],     a[mf], &bh[nf2][0]);
                    mma16816(acc[mf][2 * nf2 + 1], a[mf], &bh[nf2][2]);
                }
            // pass 2: Ah * Wl
            #pragma unroll
            for (int mf = 0; mf < 4; mf++)
                #pragma unroll
                for (int nf2 = 0; nf2 < 2; nf2++) {
                    mma16816(acc[mf][2 * nf2],     a[mf], &bl[nf2][0]);
                    mma16816(acc[mf][2 * nf2 + 1], a[mf], &bl[nf2][2]);
                }
            // pass 3: Al * Wh (Ah dead -> compiler reuses a[])
            #pragma unroll
            for (int mf = 0; mf < 4; mf++)
                ldsm4(a[mf], st + STG_T + aRow + (uint32_t)mf * 16 * ROWB + ko);
            #pragma unroll
            for (int mf = 0; mf < 4; mf++)
                #pragma unroll
                for (int nf2 = 0; nf2 < 2; nf2++) {
                    mma16816(acc[mf][2 * nf2],     a[mf], &bh[nf2][0]);
                    mma16816(acc[mf][2 * nf2 + 1], a[mf], &bh[nf2][2]);
                }
        }
        __syncthreads();
        if (c + 2 < KC) load_stage(c + 2, s);
        else cp_commit();   // keep group-count invariant for cp_wait1
    }

    // ---- epilogue ----
    const size_t co = g * (size_t)M * N;
    const float* bp = bias + g * N;
    #pragma unroll
    for (int mf = 0; mf < 4; mf++) {
        const int r0 = m0 + wm * 64 + mf * 16 + (lane >> 2);
        #pragma unroll
        for (int nf = 0; nf < 4; nf++) {
            const int cb = n0 + wn * 32 + nf * 8 + (lane & 3) * 2;
            const float b0 = bp[cb], b1 = bp[cb + 1];
            const float y00 = acc[mf][nf][0] + b0, y01 = acc[mf][nf][1] + b1;
            const float y10 = acc[mf][nf][2] + b0, y11 = acc[mf][nf][3] + b1;
            const size_t o0 = co + (size_t)r0 * N + cb;
            const size_t o1 = co + (size_t)(r0 + 8) * N + cb;
            if (wantF32) {
                *(float2*)(Cf + o0) = make_float2(y00, y01);
                *(float2*)(Cf + o1) = make_float2(y10, y11);
            } else {
                split_store(Chi, Clo, o0, y00, y01);
                split_store(Chi, Clo, o1, y10, y11);
            }
        }
    }
}

// ---------------------------------------------------------------------------
extern "C" void kernel_launch(void* const* d_in, const int* in_sizes, int n_in,
                              void* d_out, int out_size)
{
    (void)in_sizes; (void)n_in; (void)out_size;
    const float* x  = (const float*)d_in[0];
    const float* w1 = (const float*)d_in[1];
    const float* b1 = (const float*)d_in[2];
    const float* w2 = (const float*)d_in[3];
    const float* b2 = (const float*)d_in[4];
    const float* g1w[2] = { (const float*)d_in[5],  (const float*)d_in[9]  };
    const float* g1b[2] = { (const float*)d_in[6],  (const float*)d_in[10] };
    const float* g2w[2] = { (const float*)d_in[7],  (const float*)d_in[11] };
    const float* g2b[2] = { (const float*)d_in[8],  (const float*)d_in[12] };
    float* out = (float*)d_out;

    __nv_bfloat16 *whi, *wlo, *aAhi, *aAlo, *aBhi, *aBlo;
    cudaGetSymbolAddress((void**)&whi,  g_whi);
    cudaGetSymbolAddress((void**)&wlo,  g_wlo);
    cudaGetSymbolAddress((void**)&aAhi, g_aAhi);
    cudaGetSymbolAddress((void**)&aAlo, g_aAlo);
    cudaGetSymbolAddress((void**)&aBhi, g_aBhi);
    cudaGetSymbolAddress((void**)&aBlo, g_aBlo);

    const size_t OW1 = 0, OW2 = 8388608;
    const size_t OG[4] = { 16777216, 50331648, 83886080, 117440512 };

    cudaFuncSetAttribute(gemm3x, cudaFuncAttributeMaxDynamicSharedMemorySize, SMEM_SZ);

    auto conv = [&](const float* src, __nv_bfloat16* h, __nv_bfloat16* l, size_t n) {
        int n4 = (int)(n / 4);
        conv_split<<<(n4 + 255) / 256, 256>>>((const float4*)src, h, l, n4);
    };
    conv(x,      aBhi,        aBlo,        (size_t)T_TOK * HID);
    conv(w1,     whi + OW1,   wlo + OW1,   (size_t)IMM * HID);
    conv(w2,     whi + OW2,   wlo + OW2,   (size_t)HID * IMM);
    conv(g1w[0], whi + OG[0], wlo + OG[0], (size_t)4 * IMM * HID);
    conv(g2w[0], whi + OG[1], wlo + OG[1], (size_t)4 * HID * IMM);
    conv(g1w[1], whi + OG[2], wlo + OG[2], (size_t)4 * IMM * HID);
    conv(g2w[1], whi + OG[3], wlo + OG[3], (size_t)4 * HID * IMM);

    const int Mg = T_TOK / 4;
    dim3 blk(256);

    // 1) x @ w1^T -> actA  [16384, 4096]
    gemm3x<<<dim3(IMM / BN, T_TOK / BM, 1), blk, SMEM_SZ>>>(
        aBhi, aBlo, whi + OW1, wlo + OW1, b1, nullptr, aAhi, aAlo,
        T_TOK, IMM, HID, 0);
    // 2) actA @ w2^T -> actB  [16384, 2048]
    gemm3x<<<dim3(HID / BN, T_TOK / BM, 1), blk, SMEM_SZ>>>(
        aAhi, aAlo, whi + OW2, wlo + OW2, b2, nullptr, aBhi, aBlo,
        T_TOK, HID, IMM, 0);
    // 3..6) two grouped-MLP layers
    for (int li = 0; li < 2; li++) {
        gemm3x<<<dim3(IMM / BN, Mg / BM, 4), blk, SMEM_SZ>>>(
            aBhi, aBlo, whi + OG[2 * li], wlo + OG[2 * li], g1b[li],
            nullptr, aAhi, aAlo, Mg, IMM, HID, 0);
        int fin = (li == 1);
        gemm3x<<<dim3(HID / BN, Mg / BM, 4), blk, SMEM_SZ>>>(
            aAhi, aAlo, whi + OG[2 * li + 1], wlo + OG[2 * li + 1], g2b[li],
            fin ? out : nullptr, aBhi, aBlo, Mg, HID, IMM, fin);
    }
}

// round 9
// speedup vs baseline: 3.1395x; 1.3298x over previous
#include <cuda_runtime.h>
#include <cuda_fp16.h>
#include <cstdint>

// ---------------------------------------------------------------------------
// 6 chained GEMMs C = A @ W^T + b via split-fp16 (2-pass) mma.sync HMMA:
//   A = Ah + Al (fp16 pair, exact to 2^-24),  W ~= Wh (single fp16)
//   C = (Ah + Al) @ Wh   -- only error is dropped A*Wl (~2^-12/sqrt(3) rel,
//   dot-product cancellation over K) => ~1.4e-4/stage, ~3.4e-4 total.
// R9: mma.sync bf16 runs ~rt=8/SMSP on sm_103 (legacy tensor path); R8 showed
// we sit at 71% of that 8.6ms floor. Cutting 3 passes -> 2 drops the floor to
// 5.7ms. CTA 128x128, 8 warps of 64x32, 2 CTAs/SM, 2-stage cp.async.
// ---------------------------------------------------------------------------

#define BM 128
#define BN 128
#define BKC 32
#define ROWB 80u            // padded smem row stride (32 fp16 = 64B + 16B pad)
#define STG_T   10240u      // one 128x32 fp16 tile: 128 rows * 80B
#define STG_BYTES 30720u    // Ah + Al + Wh (3 tiles)
#define SMEM_SZ (2u * STG_BYTES)

static const int T_TOK = 16384, HID = 2048, IMM = 4096;

// ---- scratch (__device__ globals; allocation-guard-safe) ----
__device__ __half g_wh[150994944];           // all weights, fp16 (302 MB)
__device__ __half g_aAhi[67108864];          // 16384 x 4096 activations
__device__ __half g_aAlo[67108864];
__device__ __half g_aBhi[33554432];          // 16384 x 2048 activations
__device__ __half g_aBlo[33554432];

__device__ __forceinline__ uint32_t smem_u32(const void* p) {
    uint32_t a;
    asm("{ .reg .u64 t; cvta.to.shared.u64 t, %1; cvt.u32.u64 %0, t; }" : "=r"(a) : "l"(p));
    return a;
}
__device__ __forceinline__ void cp16(uint32_t dst, const void* src) {
    asm volatile("cp.async.cg.shared.global [%0], [%1], 16;" :: "r"(dst), "l"(src));
}
__device__ __forceinline__ void cp_commit() {
    asm volatile("cp.async.commit_group;" ::: "memory");
}
__device__ __forceinline__ void cp_wait1() {
    asm volatile("cp.async.wait_group 1;" ::: "memory");
}
__device__ __forceinline__ void ldsm4(uint32_t* r, uint32_t a) {
    asm volatile("ldmatrix.sync.aligned.m8n8.x4.shared.b16 {%0,%1,%2,%3}, [%4];"
                 : "=r"(r[0]), "=r"(r[1]), "=r"(r[2]), "=r"(r[3]) : "r"(a));
}
__device__ __forceinline__ void mma16816(float* d, const uint32_t* a, const uint32_t* b) {
    asm volatile("mma.sync.aligned.m16n8k16.row.col.f32.f16.f16.f32 "
                 "{%0,%1,%2,%3}, {%4,%5,%6,%7}, {%8,%9}, {%0,%1,%2,%3};"
                 : "+f"(d[0]), "+f"(d[1]), "+f"(d[2]), "+f"(d[3])
                 : "r"(a[0]), "r"(a[1]), "r"(a[2]), "r"(a[3]), "r"(b[0]), "r"(b[1]));
}

// ---- fp32 -> (fp16 hi, fp16 lo) split (activations) ----
__global__ void conv_split(const float4* __restrict__ in,
                           __half* __restrict__ hi,
                           __half* __restrict__ lo, int n4)
{
    int i = blockIdx.x * blockDim.x + threadIdx.x;
    if (i >= n4) return;
    float4 v = in[i];
    __half h0 = __float2half(v.x), h1 = __float2half(v.y);
    __half h2 = __float2half(v.z), h3 = __float2half(v.w);
    __half l0 = __float2half(v.x - __half2float(h0));
    __half l1 = __float2half(v.y - __half2float(h1));
    __half l2 = __float2half(v.z - __half2float(h2));
    __half l3 = __float2half(v.w - __half2float(h3));
    uint2 hp, lp;
    hp.x = (uint32_t)__half_as_ushort(h0) | ((uint32_t)__half_as_ushort(h1) << 16);
    hp.y = (uint32_t)__half_as_ushort(h2) | ((uint32_t)__half_as_ushort(h3) << 16);
    lp.x = (uint32_t)__half_as_ushort(l0) | ((uint32_t)__half_as_ushort(l1) << 16);
    lp.y = (uint32_t)__half_as_ushort(l2) | ((uint32_t)__half_as_ushort(l3) << 16);
    ((uint2*)hi)[i] = hp;
    ((uint2*)lo)[i] = lp;
}

// ---- fp32 -> fp16 (weights, single) ----
__global__ void conv_h(const float4* __restrict__ in, __half* __restrict__ o, int n4)
{
    int i = blockIdx.x * blockDim.x + threadIdx.x;
    if (i >= n4) return;
    float4 v = in[i];
    uint2 p;
    p.x = (uint32_t)__half_as_ushort(__float2half(v.x))
        | ((uint32_t)__half_as_ushort(__float2half(v.y)) << 16);
    p.y = (uint32_t)__half_as_ushort(__float2half(v.z))
        | ((uint32_t)__half_as_ushort(__float2half(v.w)) << 16);
    ((uint2*)o)[i] = p;
}

__device__ __forceinline__ void split_store(__half* __restrict__ hi,
                                            __half* __restrict__ lo,
                                            size_t off, float y0, float y1)
{
    __half h0 = __float2half(y0), h1 = __float2half(y1);
    __half l0 = __float2half(y0 - __half2float(h0));
    __half l1 = __float2half(y1 - __half2float(h1));
    *(uint32_t*)(hi + off) =
        (uint32_t)__half_as_ushort(h0) | ((uint32_t)__half_as_ushort(h1) << 16);
    *(uint32_t*)(lo + off) =
        (uint32_t)__half_as_ushort(l0) | ((uint32_t)__half_as_ushort(l1) << 16);
}

// C[M,N] = (Ah+Al)[M,K] @ Wh[N,K]^T + bias; grouped via blockIdx.z.
__global__ void __launch_bounds__(256, 2)
gemm2x(const __half* __restrict__ Ah, const __half* __restrict__ Al,
       const __half* __restrict__ Wh,
       const float* __restrict__ bias, float* __restrict__ Cf,
       __half* __restrict__ Chi, __half* __restrict__ Clo,
       int M, int N, int K, int wantF32)
{
    extern __shared__ char smem[];
    const uint32_t sb = smem_u32(smem);

    const int tid  = threadIdx.x;
    const int lane = tid & 31;
    const int warp = tid >> 5;
    const int wm   = warp >> 2;   // 0..1 -> m offset 64
    const int wn   = warp & 3;    // 0..3 -> n offset 32
    const size_t g = blockIdx.z;
    const int n0 = blockIdx.x * BN;
    const int m0 = blockIdx.y * BM;

    const __half* Agh = Ah + g * (size_t)M * K + (size_t)m0 * K;
    const __half* Agl = Al + g * (size_t)M * K + (size_t)m0 * K;
    const __half* Wgh = Wh + g * (size_t)N * K + (size_t)n0 * K;

    // one stage = 3 tiles x 512 x 16B = 1536 cp16; 6 per thread
    auto load_stage = [&](int c, int s) {
        const uint32_t st = sb + (uint32_t)s * STG_BYTES;
        const size_t kof = (size_t)c * BKC;
        #pragma unroll
        for (int i = 0; i < 6; i++) {
            int l = i * 256 + tid;
            const __half* src;
            uint32_t base;
            int t;
            if (i < 2)      { t = l;        src = Agh; base = st; }
            else if (i < 4) { t = l - 512;  src = Agl; base = st + STG_T; }
            else            { t = l - 1024; src = Wgh; base = st + 2 * STG_T; }
            int row = t >> 2, cc = t & 3;
            cp16(base + (uint32_t)row * ROWB + (uint32_t)cc * 16,
                 src + (size_t)row * K + kof + cc * 8);
        }
        cp_commit();
    };

    float acc[4][4][4];
    #pragma unroll
    for (int mf = 0; mf < 4; mf++)
        #pragma unroll
        for (int nf = 0; nf < 4; nf++)
            #pragma unroll
            for (int q = 0; q < 4; q++) acc[mf][nf][q] = 0.f;

    const int KC = K / BKC;
    load_stage(0, 0);
    load_stage(1, 1);

    // ldmatrix base addresses (non-trans; both operands K-major)
    const uint32_t aRow = (uint32_t)(wm * 64 + (lane & 15)) * ROWB + (uint32_t)(lane >> 4) * 16;
    const uint32_t bRow = (uint32_t)(wn * 32 + ((lane >> 4) << 3) + (lane & 7)) * ROWB
                        + (uint32_t)((lane >> 3) & 1) * 16;

    for (int c = 0; c < KC; c++) {
        const int s = c & 1;
        const uint32_t st = sb + (uint32_t)s * STG_BYTES;
        cp_wait1();
        __syncthreads();

        #pragma unroll
        for (int ks = 0; ks < 2; ks++) {
            const uint32_t ko = (uint32_t)ks * 32;  // 16 fp16 = 32B
            uint32_t a[4][4], bh[2][4];
            // Ah (m64 x k16) + Wh (n32 x k16)
            #pragma unroll
            for (int mf = 0; mf < 4; mf++)
                ldsm4(a[mf], st + aRow + (uint32_t)mf * 16 * ROWB + ko);
            #pragma unroll
            for (int nf2 = 0; nf2 < 2; nf2++)
                ldsm4(bh[nf2], st + 2 * STG_T + bRow + (uint32_t)nf2 * 16 * ROWB + ko);
            // pass 1: Ah * Wh
            #pragma unroll
            for (int mf = 0; mf < 4; mf++)
                #pragma unroll
                for (int nf2 = 0; nf2 < 2; nf2++) {
                    mma16816(acc[mf][2 * nf2],     a[mf], &bh[nf2][0]);
                    mma16816(acc[mf][2 * nf2 + 1], a[mf], &bh[nf2][2]);
                }
            // pass 2: Al * Wh (Ah dead -> regs reused)
            #pragma unroll
            for (int mf = 0; mf < 4; mf++)
                ldsm4(a[mf], st + STG_T + aRow + (uint32_t)mf * 16 * ROWB + ko);
            #pragma unroll
            for (int mf = 0; mf < 4; mf++)
                #pragma unroll
                for (int nf2 = 0; nf2 < 2; nf2++) {
                    mma16816(acc[mf][2 * nf2],     a[mf], &bh[nf2][0]);
                    mma16816(acc[mf][2 * nf2 + 1], a[mf], &bh[nf2][2]);
                }
        }
        __syncthreads();
        if (c + 2 < KC) load_stage(c + 2, s);
        else cp_commit();   // keep group-count invariant for cp_wait1
    }

    // ---- epilogue ----
    const size_t co = g * (size_t)M * N;
    const float* bp = bias + g * N;
    #pragma unroll
    for (int mf = 0; mf < 4; mf++) {
        const int r0 = m0 + wm * 64 + mf * 16 + (lane >> 2);
        #pragma unroll
        for (int nf = 0; nf < 4; nf++) {
            const int cb = n0 + wn * 32 + nf * 8 + (lane & 3) * 2;
            const float b0 = bp[cb], b1 = bp[cb + 1];
            const float y00 = acc[mf][nf][0] + b0, y01 = acc[mf][nf][1] + b1;
            const float y10 = acc[mf][nf][2] + b0, y11 = acc[mf][nf][3] + b1;
            const size_t o0 = co + (size_t)r0 * N + cb;
            const size_t o1 = co + (size_t)(r0 + 8) * N + cb;
            if (wantF32) {
                *(float2*)(Cf + o0) = make_float2(y00, y01);
                *(float2*)(Cf + o1) = make_float2(y10, y11);
            } else {
                split_store(Chi, Clo, o0, y00, y01);
                split_store(Chi, Clo, o1, y10, y11);
            }
        }
    }
}

// ---------------------------------------------------------------------------
extern "C" void kernel_launch(void* const* d_in, const int* in_sizes, int n_in,
                              void* d_out, int out_size)
{
    (void)in_sizes; (void)n_in; (void)out_size;
    const float* x  = (const float*)d_in[0];
    const float* w1 = (const float*)d_in[1];
    const float* b1 = (const float*)d_in[2];
    const float* w2 = (const float*)d_in[3];
    const float* b2 = (const float*)d_in[4];
    const float* g1w[2] = { (const float*)d_in[5],  (const float*)d_in[9]  };
    const float* g1b[2] = { (const float*)d_in[6],  (const float*)d_in[10] };
    const float* g2w[2] = { (const float*)d_in[7],  (const float*)d_in[11] };
    const float* g2b[2] = { (const float*)d_in[8],  (const float*)d_in[12] };
    float* out = (float*)d_out;

    __half *wh, *aAhi, *aAlo, *aBhi, *aBlo;
    cudaGetSymbolAddress((void**)&wh,   g_wh);
    cudaGetSymbolAddress((void**)&aAhi, g_aAhi);
    cudaGetSymbolAddress((void**)&aAlo, g_aAlo);
    cudaGetSymbolAddress((void**)&aBhi, g_aBhi);
    cudaGetSymbolAddress((void**)&aBlo, g_aBlo);

    const size_t OW1 = 0, OW2 = 8388608;
    const size_t OG[4] = { 16777216, 50331648, 83886080, 117440512 };

    cudaFuncSetAttribute(gemm2x, cudaFuncAttributeMaxDynamicSharedMemorySize, SMEM_SZ);

    // activations: hi/lo split; weights: single fp16
    {
        int n4 = (int)((size_t)T_TOK * HID / 4);
        conv_split<<<(n4 + 255) / 256, 256>>>((const float4*)x, aBhi, aBlo, n4);
    }
    auto convw = [&](const float* src, __half* dst, size_t n) {
        int n4 = (int)(n / 4);
        conv_h<<<(n4 + 255) / 256, 256>>>((const float4*)src, dst, n4);
    };
    convw(w1,     wh + OW1,   (size_t)IMM * HID);
    convw(w2,     wh + OW2,   (size_t)HID * IMM);
    convw(g1w[0], wh + OG[0], (size_t)4 * IMM * HID);
    convw(g2w[0], wh + OG[1], (size_t)4 * HID * IMM);
    convw(g1w[1], wh + OG[2], (size_t)4 * IMM * HID);
    convw(g2w[1], wh + OG[3], (size_t)4 * HID * IMM);

    const int Mg = T_TOK / 4;
    dim3 blk(256);

    // 1) x @ w1^T -> actA  [16384, 4096]
    gemm2x<<<dim3(IMM / BN, T_TOK / BM, 1), blk, SMEM_SZ>>>(
        aBhi, aBlo, wh + OW1, b1, nullptr, aAhi, aAlo,
        T_TOK, IMM, HID, 0);
    // 2) actA @ w2^T -> actB  [16384, 2048]
    gemm2x<<<dim3(HID / BN, T_TOK / BM, 1), blk, SMEM_SZ>>>(
        aAhi, aAlo, wh + OW2, b2, nullptr, aBhi, aBlo,
        T_TOK, HID, IMM, 0);
    // 3..6) two grouped-MLP layers
    for (int li = 0; li < 2; li++) {
        gemm2x<<<dim3(IMM / BN, Mg / BM, 4), blk, SMEM_SZ>>>(
            aBhi, aBlo, wh + OG[2 * li], g1b[li],
            nullptr, aAhi, aAlo, Mg, IMM, HID, 0);
        int fin = (li == 1);
        gemm2x<<<dim3(HID / BN, Mg / BM, 4), blk, SMEM_SZ>>>(
            aAhi, aAlo, wh + OG[2 * li + 1], g2b[li],
            fin ? out : nullptr, aBhi, aBlo, Mg, HID, IMM, fin);
    }
}

// round 10
// speedup vs baseline: 3.6541x; 1.1639x over previous
#include <cuda_runtime.h>
#include <cuda_fp16.h>
#include <cstdint>

// ---------------------------------------------------------------------------
// 6 chained GEMMs C = A @ W^T + b via split-fp16 (2-pass) mma.sync HMMA.
// R10: split the WEIGHTS (W = Wh + Wl), keep activations single fp16:
//   C = A_fp16 @ (Wh + Wl)^T   -- error = eps(A)*W ~ 2^-12, cancels over K,
//   statistically identical to R9's A-split (measured 5.1e-4 total).
// Wins vs R9: A fragments LDS'd once per k16 (reused across both passes),
// activations single fp16 (half act traffic, trivial epilogue), BKC=64
// halves barrier count. ROWB=144 keeps ldsm + STS conflict-free.
// CTA 128x128, 8 warps of 64x32, 2 CTAs/SM, 2-stage cp.async.
// ---------------------------------------------------------------------------

#define BM 128
#define BN 128
#define BKC 64
#define ROWB 144u           // 64 fp16 = 128B data + 16B pad (9 x 16B units)
#define TILE_B 18432u       // 128 rows * 144B
#define STG_BYTES 55296u    // A + Wh + Wl (3 tiles)
#define SMEM_SZ (2u * STG_BYTES)

static const int T_TOK = 16384, HID = 2048, IMM = 4096;

// ---- scratch (__device__ globals; allocation-guard-safe) ----
__device__ __half g_whi[150994944];          // weights hi (302 MB)
__device__ __half g_wlo[150994944];          // weights lo
__device__ __half g_aA[67108864];            // 16384 x 4096 activations (single)
__device__ __half g_aB[33554432];            // 16384 x 2048 activations (single)

__device__ __forceinline__ uint32_t smem_u32(const void* p) {
    uint32_t a;
    asm("{ .reg .u64 t; cvta.to.shared.u64 t, %1; cvt.u32.u64 %0, t; }" : "=r"(a) : "l"(p));
    return a;
}
__device__ __forceinline__ void cp16(uint32_t dst, const void* src) {
    asm volatile("cp.async.cg.shared.global [%0], [%1], 16;" :: "r"(dst), "l"(src));
}
__device__ __forceinline__ void cp_commit() {
    asm volatile("cp.async.commit_group;" ::: "memory");
}
__device__ __forceinline__ void cp_wait1() {
    asm volatile("cp.async.wait_group 1;" ::: "memory");
}
__device__ __forceinline__ void ldsm4(uint32_t* r, uint32_t a) {
    asm volatile("ldmatrix.sync.aligned.m8n8.x4.shared.b16 {%0,%1,%2,%3}, [%4];"
                 : "=r"(r[0]), "=r"(r[1]), "=r"(r[2]), "=r"(r[3]) : "r"(a));
}
__device__ __forceinline__ void mma16816(float* d, const uint32_t* a, const uint32_t* b) {
    asm volatile("mma.sync.aligned.m16n8k16.row.col.f32.f16.f16.f32 "
                 "{%0,%1,%2,%3}, {%4,%5,%6,%7}, {%8,%9}, {%0,%1,%2,%3};"
                 : "+f"(d[0]), "+f"(d[1]), "+f"(d[2]), "+f"(d[3])
                 : "r"(a[0]), "r"(a[1]), "r"(a[2]), "r"(a[3]), "r"(b[0]), "r"(b[1]));
}

// ---- fp32 -> fp16 (activations / x) ----
__global__ void conv_h(const float4* __restrict__ in, __half* __restrict__ o, int n4)
{
    int i = blockIdx.x * blockDim.x + threadIdx.x;
    if (i >= n4) return;
    float4 v = in[i];
    uint2 p;
    p.x = (uint32_t)__half_as_ushort(__float2half(v.x))
        | ((uint32_t)__half_as_ushort(__float2half(v.y)) << 16);
    p.y = (uint32_t)__half_as_ushort(__float2half(v.z))
        | ((uint32_t)__half_as_ushort(__float2half(v.w)) << 16);
    ((uint2*)o)[i] = p;
}

// ---- fp32 -> (fp16 hi, fp16 lo) split (weights) ----
__global__ void conv_split(const float4* __restrict__ in,
                           __half* __restrict__ hi,
                           __half* __restrict__ lo, int n4)
{
    int i = blockIdx.x * blockDim.x + threadIdx.x;
    if (i >= n4) return;
    float4 v = in[i];
    __half h0 = __float2half(v.x), h1 = __float2half(v.y);
    __half h2 = __float2half(v.z), h3 = __float2half(v.w);
    __half l0 = __float2half(v.x - __half2float(h0));
    __half l1 = __float2half(v.y - __half2float(h1));
    __half l2 = __float2half(v.z - __half2float(h2));
    __half l3 = __float2half(v.w - __half2float(h3));
    uint2 hp, lp;
    hp.x = (uint32_t)__half_as_ushort(h0) | ((uint32_t)__half_as_ushort(h1) << 16);
    hp.y = (uint32_t)__half_as_ushort(h2) | ((uint32_t)__half_as_ushort(h3) << 16);
    lp.x = (uint32_t)__half_as_ushort(l0) | ((uint32_t)__half_as_ushort(l1) << 16);
    lp.y = (uint32_t)__half_as_ushort(l2) | ((uint32_t)__half_as_ushort(l3) << 16);
    ((uint2*)hi)[i] = hp;
    ((uint2*)lo)[i] = lp;
}

// C[M,N] = A[M,K] @ (Wh+Wl)[N,K]^T + bias; grouped via blockIdx.z.
__global__ void __launch_bounds__(256, 2)
gemm2w(const __half* __restrict__ A,
       const __half* __restrict__ Wh, const __half* __restrict__ Wl,
       const float* __restrict__ bias, float* __restrict__ Cf,
       __half* __restrict__ Ch,
       int M, int N, int K, int wantF32)
{
    extern __shared__ char smem[];
    const uint32_t sb = smem_u32(smem);

    const int tid  = threadIdx.x;
    const int lane = tid & 31;
    const int warp = tid >> 5;
    const int wm   = warp >> 2;   // 0..1 -> m offset 64
    const int wn   = warp & 3;    // 0..3 -> n offset 32
    const size_t g = blockIdx.z;
    const int n0 = blockIdx.x * BN;
    const int m0 = blockIdx.y * BM;

    const __half* Ag  = A  + g * (size_t)M * K + (size_t)m0 * K;
    const __half* Wgh = Wh + g * (size_t)N * K + (size_t)n0 * K;
    const __half* Wgl = Wl + g * (size_t)N * K + (size_t)n0 * K;

    // one stage = 3 tiles x 128 rows x 8 units = 3072 cp16; 12 per thread
    auto load_stage = [&](int c, int s) {
        const uint32_t st = sb + (uint32_t)s * STG_BYTES;
        const size_t kof = (size_t)c * BKC;
        #pragma unroll
        for (int i = 0; i < 12; i++) {
            int l = i * 256 + tid;
            const __half* src;
            uint32_t base;
            int t;
            if (i < 4)      { t = l;        src = Ag;  base = st; }
            else if (i < 8) { t = l - 1024; src = Wgh; base = st + TILE_B; }
            else            { t = l - 2048; src = Wgl; base = st + 2 * TILE_B; }
            int row = t >> 3, c8 = t & 7;
            cp16(base + (uint32_t)row * ROWB + (uint32_t)c8 * 16,
                 src + (size_t)row * K + kof + c8 * 8);
        }
        cp_commit();
    };

    float acc[4][4][4];
    #pragma unroll
    for (int mf = 0; mf < 4; mf++)
        #pragma unroll
        for (int nf = 0; nf < 4; nf++)
            #pragma unroll
            for (int q = 0; q < 4; q++) acc[mf][nf][q] = 0.f;

    const int KC = K / BKC;
    load_stage(0, 0);
    load_stage(1, 1);

    // ldmatrix base addresses (non-trans; both operands K-major)
    const uint32_t aRow = (uint32_t)(wm * 64 + (lane & 15)) * ROWB + (uint32_t)(lane >> 4) * 16;
    const uint32_t bRow = (uint32_t)(wn * 32 + ((lane >> 4) << 3) + (lane & 7)) * ROWB
                        + (uint32_t)((lane >> 3) & 1) * 16;

    for (int c = 0; c < KC; c++) {
        const int s = c & 1;
        const uint32_t st = sb + (uint32_t)s * STG_BYTES;
        cp_wait1();
        __syncthreads();

        #pragma unroll
        for (int ks = 0; ks < 4; ks++) {
            const uint32_t ko = (uint32_t)ks * 32;  // 16 fp16 = 32B
            uint32_t a[4][4], bh[2][4], bl[2][4];
            // A (m64 x k16) loaded ONCE, reused for both passes
            #pragma unroll
            for (int mf = 0; mf < 4; mf++)
                ldsm4(a[mf], st + aRow + (uint32_t)mf * 16 * ROWB + ko);
            #pragma unroll
            for (int nf2 = 0; nf2 < 2; nf2++)
                ldsm4(bh[nf2], st + TILE_B + bRow + (uint32_t)nf2 * 16 * ROWB + ko);
            #pragma unroll
            for (int nf2 = 0; nf2 < 2; nf2++)
                ldsm4(bl[nf2], st + 2 * TILE_B + bRow + (uint32_t)nf2 * 16 * ROWB + ko);
            // pass 1: A * Wh
            #pragma unroll
            for (int mf = 0; mf < 4; mf++)
                #pragma unroll
                for (int nf2 = 0; nf2 < 2; nf2++) {
                    mma16816(acc[mf][2 * nf2],     a[mf], &bh[nf2][0]);
                    mma16816(acc[mf][2 * nf2 + 1], a[mf], &bh[nf2][2]);
                }
            // pass 2: A * Wl
            #pragma unroll
            for (int mf = 0; mf < 4; mf++)
                #pragma unroll
                for (int nf2 = 0; nf2 < 2; nf2++) {
                    mma16816(acc[mf][2 * nf2],     a[mf], &bl[nf2][0]);
                    mma16816(acc[mf][2 * nf2 + 1], a[mf], &bl[nf2][2]);
                }
        }
        __syncthreads();
        if (c + 2 < KC) load_stage(c + 2, s);
        else cp_commit();   // keep group-count invariant for cp_wait1
    }

    // ---- epilogue ----
    const size_t co = g * (size_t)M * N;
    const float* bp = bias + g * N;
    #pragma unroll
    for (int mf = 0; mf < 4; mf++) {
        const int r0 = m0 + wm * 64 + mf * 16 + (lane >> 2);
        #pragma unroll
        for (int nf = 0; nf < 4; nf++) {
            const int cb = n0 + wn * 32 + nf * 8 + (lane & 3) * 2;
            const float b0 = bp[cb], b1 = bp[cb + 1];
            const float y00 = acc[mf][nf][0] + b0, y01 = acc[mf][nf][1] + b1;
            const float y10 = acc[mf][nf][2] + b0, y11 = acc[mf][nf][3] + b1;
            const size_t o0 = co + (size_t)r0 * N + cb;
            const size_t o1 = co + (size_t)(r0 + 8) * N + cb;
            if (wantF32) {
                *(float2*)(Cf + o0) = make_float2(y00, y01);
                *(float2*)(Cf + o1) = make_float2(y10, y11);
            } else {
                *(uint32_t*)(Ch + o0) =
                    (uint32_t)__half_as_ushort(__float2half(y00))
                  | ((uint32_t)__half_as_ushort(__float2half(y01)) << 16);
                *(uint32_t*)(Ch + o1) =
                    (uint32_t)__half_as_ushort(__float2half(y10))
                  | ((uint32_t)__half_as_ushort(__float2half(y11)) << 16);
            }
        }
    }
}

// ---------------------------------------------------------------------------
extern "C" void kernel_launch(void* const* d_in, const int* in_sizes, int n_in,
                              void* d_out, int out_size)
{
    (void)in_sizes; (void)n_in; (void)out_size;
    const float* x  = (const float*)d_in[0];
    const float* w1 = (const float*)d_in[1];
    const float* b1 = (const float*)d_in[2];
    const float* w2 = (const float*)d_in[3];
    const float* b2 = (const float*)d_in[4];
    const float* g1w[2] = { (const float*)d_in[5],  (const float*)d_in[9]  };
    const float* g1b[2] = { (const float*)d_in[6],  (const float*)d_in[10] };
    const float* g2w[2] = { (const float*)d_in[7],  (const float*)d_in[11] };
    const float* g2b[2] = { (const float*)d_in[8],  (const float*)d_in[12] };
    float* out = (float*)d_out;

    __half *whi, *wlo, *aA, *aB;
    cudaGetSymbolAddress((void**)&whi, g_whi);
    cudaGetSymbolAddress((void**)&wlo, g_wlo);
    cudaGetSymbolAddress((void**)&aA,  g_aA);
    cudaGetSymbolAddress((void**)&aB,  g_aB);

    const size_t OW1 = 0, OW2 = 8388608;
    const size_t OG[4] = { 16777216, 50331648, 83886080, 117440512 };

    cudaFuncSetAttribute(gemm2w, cudaFuncAttributeMaxDynamicSharedMemorySize, SMEM_SZ);

    // x -> single fp16; weights -> hi/lo split
    {
        int n4 = (int)((size_t)T_TOK * HID / 4);
        conv_h<<<(n4 + 255) / 256, 256>>>((const float4*)x, aB, n4);
    }
    auto convw = [&](const float* src, size_t off, size_t n) {
        int n4 = (int)(n / 4);
        conv_split<<<(n4 + 255) / 256, 256>>>((const float4*)src, whi + off, wlo + off, n4);
    };
    convw(w1,     OW1,   (size_t)IMM * HID);
    convw(w2,     OW2,   (size_t)HID * IMM);
    convw(g1w[0], OG[0], (size_t)4 * IMM * HID);
    convw(g2w[0], OG[1], (size_t)4 * HID * IMM);
    convw(g1w[1], OG[2], (size_t)4 * IMM * HID);
    convw(g2w[1], OG[3], (size_t)4 * HID * IMM);

    const int Mg = T_TOK / 4;
    dim3 blk(256);

    // 1) x @ w1^T -> actA  [16384, 4096]
    gemm2w<<<dim3(IMM / BN, T_TOK / BM, 1), blk, SMEM_SZ>>>(
        aB, whi + OW1, wlo + OW1, b1, nullptr, aA, T_TOK, IMM, HID, 0);
    // 2) actA @ w2^T -> actB  [16384, 2048]
    gemm2w<<<dim3(HID / BN, T_TOK / BM, 1), blk, SMEM_SZ>>>(
        aA, whi + OW2, wlo + OW2, b2, nullptr, aB, T_TOK, HID, IMM, 0);
    // 3..6) two grouped-MLP layers
    for (int li = 0; li < 2; li++) {
        gemm2w<<<dim3(IMM / BN, Mg / BM, 4), blk, SMEM_SZ>>>(
            aB, whi + OG[2 * li], wlo + OG[2 * li], g1b[li],
            nullptr, aA, Mg, IMM, HID, 0);
        int fin = (li == 1);
        gemm2w<<<dim3(HID / BN, Mg / BM, 4), blk, SMEM_SZ>>>(
            aA, whi + OG[2 * li + 1], wlo + OG[2 * li + 1], g2b[li],
            fin ? out : nullptr, aB, Mg, HID, IMM, fin);
    }
}

// round 11
// speedup vs baseline: 6.6661x; 1.8243x over previous
#include <cuda_runtime.h>
#include <cuda_fp16.h>
#include <cstdint>

// ---------------------------------------------------------------------------
// 6 chained GEMMs C = A @ W^T + b via single-pass fp16 mma.sync HMMA.
// R11: calibrated error model (R9/R10 both measured 5.1e-4 with ONE rounded
// operand => 2.08e-4/stage) says rounding BOTH operands gives sqrt(2) more:
// ~2.94e-4/stage, sqrt(6)*~= 7.2e-4 total < 1e-3. So drop the Wl pass:
// MMA work halves (floor 6.05 -> 3.0ms), stage = 2 tiles -> 3-stage pipeline
// at 2 CTAs/SM. CTA 128x128, 8 warps of 64x32, BKC=64.
// ---------------------------------------------------------------------------

#define BM 128
#define BN 128
#define BKC 64
#define ROWB 144u           // 64 fp16 = 128B data + 16B pad (9 x 16B units)
#define TILE_B 18432u       // 128 rows * 144B
#define STG_BYTES 36864u    // A + W (2 tiles)
#define NSTG 3
#define SMEM_SZ (NSTG * STG_BYTES)

static const int T_TOK = 16384, HID = 2048, IMM = 4096;

// ---- scratch (__device__ globals; allocation-guard-safe) ----
__device__ __half g_wh[150994944];           // all weights fp16 (302 MB)
__device__ __half g_aA[67108864];            // 16384 x 4096 activations
__device__ __half g_aB[33554432];            // 16384 x 2048 activations

__device__ __forceinline__ uint32_t smem_u32(const void* p) {
    uint32_t a;
    asm("{ .reg .u64 t; cvta.to.shared.u64 t, %1; cvt.u32.u64 %0, t; }" : "=r"(a) : "l"(p));
    return a;
}
__device__ __forceinline__ void cp16(uint32_t dst, const void* src) {
    asm volatile("cp.async.cg.shared.global [%0], [%1], 16;" :: "r"(dst), "l"(src));
}
__device__ __forceinline__ void cp_commit() {
    asm volatile("cp.async.commit_group;" ::: "memory");
}
__device__ __forceinline__ void cp_wait2() {
    asm volatile("cp.async.wait_group 2;" ::: "memory");
}
__device__ __forceinline__ void ldsm4(uint32_t* r, uint32_t a) {
    asm volatile("ldmatrix.sync.aligned.m8n8.x4.shared.b16 {%0,%1,%2,%3}, [%4];"
                 : "=r"(r[0]), "=r"(r[1]), "=r"(r[2]), "=r"(r[3]) : "r"(a));
}
__device__ __forceinline__ void mma16816(float* d, const uint32_t* a, const uint32_t* b) {
    asm volatile("mma.sync.aligned.m16n8k16.row.col.f32.f16.f16.f32 "
                 "{%0,%1,%2,%3}, {%4,%5,%6,%7}, {%8,%9}, {%0,%1,%2,%3};"
                 : "+f"(d[0]), "+f"(d[1]), "+f"(d[2]), "+f"(d[3])
                 : "r"(a[0]), "r"(a[1]), "r"(a[2]), "r"(a[3]), "r"(b[0]), "r"(b[1]));
}

// ---- fp32 -> fp16 ----
__global__ void conv_h(const float4* __restrict__ in, __half* __restrict__ o, int n4)
{
    int i = blockIdx.x * blockDim.x + threadIdx.x;
    if (i >= n4) return;
    float4 v = in[i];
    uint2 p;
    p.x = (uint32_t)__half_as_ushort(__float2half(v.x))
        | ((uint32_t)__half_as_ushort(__float2half(v.y)) << 16);
    p.y = (uint32_t)__half_as_ushort(__float2half(v.z))
        | ((uint32_t)__half_as_ushort(__float2half(v.w)) << 16);
    ((uint2*)o)[i] = p;
}

// C[M,N] = A[M,K] @ W[N,K]^T + bias; grouped via blockIdx.z.
__global__ void __launch_bounds__(256, 2)
gemm1p(const __half* __restrict__ A, const __half* __restrict__ W,
       const float* __restrict__ bias, float* __restrict__ Cf,
       __half* __restrict__ Ch,
       int M, int N, int K, int wantF32)
{
    extern __shared__ char smem[];
    const uint32_t sb = smem_u32(smem);

    const int tid  = threadIdx.x;
    const int lane = tid & 31;
    const int warp = tid >> 5;
    const int wm   = warp >> 2;   // 0..1 -> m offset 64
    const int wn   = warp & 3;    // 0..3 -> n offset 32
    const size_t g = blockIdx.z;
    const int n0 = blockIdx.x * BN;
    const int m0 = blockIdx.y * BM;

    const __half* Ag = A + g * (size_t)M * K + (size_t)m0 * K;
    const __half* Wg = W + g * (size_t)N * K + (size_t)n0 * K;

    // one stage = 2 tiles x 128 rows x 8 units = 2048 cp16; 8 per thread
    auto load_stage = [&](int c, int s) {
        const uint32_t st = sb + (uint32_t)s * STG_BYTES;
        const size_t kof = (size_t)c * BKC;
        #pragma unroll
        for (int i = 0; i < 8; i++) {
            int l = i * 256 + tid;
            const __half* src;
            uint32_t base;
            int t;
            if (i < 4) { t = l;        src = Ag; base = st; }
            else       { t = l - 1024; src = Wg; base = st + TILE_B; }
            int row = t >> 3, c8 = t & 7;
            cp16(base + (uint32_t)row * ROWB + (uint32_t)c8 * 16,
                 src + (size_t)row * K + kof + c8 * 8);
        }
        cp_commit();
    };

    float acc[4][4][4];
    #pragma unroll
    for (int mf = 0; mf < 4; mf++)
        #pragma unroll
        for (int nf = 0; nf < 4; nf++)
            #pragma unroll
            for (int q = 0; q < 4; q++) acc[mf][nf][q] = 0.f;

    const int KC = K / BKC;
    load_stage(0, 0);
    load_stage(1, 1);
    load_stage(2, 2);

    // ldmatrix base addresses (non-trans; both operands K-major)
    const uint32_t aRow = (uint32_t)(wm * 64 + (lane & 15)) * ROWB + (uint32_t)(lane >> 4) * 16;
    const uint32_t bRow = (uint32_t)(wn * 32 + ((lane >> 4) << 3) + (lane & 7)) * ROWB
                        + (uint32_t)((lane >> 3) & 1) * 16;

    int s = 0;
    for (int c = 0; c < KC; c++) {
        const uint32_t st = sb + (uint32_t)s * STG_BYTES;
        cp_wait2();
        __syncthreads();

        #pragma unroll
        for (int ks = 0; ks < 4; ks++) {
            const uint32_t ko = (uint32_t)ks * 32;  // 16 fp16 = 32B
            uint32_t a[4][4], b[2][4];
            #pragma unroll
            for (int mf = 0; mf < 4; mf++)
                ldsm4(a[mf], st + aRow + (uint32_t)mf * 16 * ROWB + ko);
            #pragma unroll
            for (int nf2 = 0; nf2 < 2; nf2++)
                ldsm4(b[nf2], st + TILE_B + bRow + (uint32_t)nf2 * 16 * ROWB + ko);
            #pragma unroll
            for (int mf = 0; mf < 4; mf++)
                #pragma unroll
                for (int nf2 = 0; nf2 < 2; nf2++) {
                    mma16816(acc[mf][2 * nf2],     a[mf], &b[nf2][0]);
                    mma16816(acc[mf][2 * nf2 + 1], a[mf], &b[nf2][2]);
                }
        }
        __syncthreads();
        if (c + NSTG < KC) load_stage(c + NSTG, s);
        else cp_commit();   // keep group-count invariant for cp_wait2
        s = (s + 1 == NSTG) ? 0 : s + 1;
    }

    // ---- epilogue ----
    const size_t co = g * (size_t)M * N;
    const float* bp = bias + g * N;
    #pragma unroll
    for (int mf = 0; mf < 4; mf++) {
        const int r0 = m0 + wm * 64 + mf * 16 + (lane >> 2);
        #pragma unroll
        for (int nf = 0; nf < 4; nf++) {
            const int cb = n0 + wn * 32 + nf * 8 + (lane & 3) * 2;
            const float b0 = bp[cb], b1 = bp[cb + 1];
            const float y00 = acc[mf][nf][0] + b0, y01 = acc[mf][nf][1] + b1;
            const float y10 = acc[mf][nf][2] + b0, y11 = acc[mf][nf][3] + b1;
            const size_t o0 = co + (size_t)r0 * N + cb;
            const size_t o1 = co + (size_t)(r0 + 8) * N + cb;
            if (wantF32) {
                *(float2*)(Cf + o0) = make_float2(y00, y01);
                *(float2*)(Cf + o1) = make_float2(y10, y11);
            } else {
                *(uint32_t*)(Ch + o0) =
                    (uint32_t)__half_as_ushort(__float2half(y00))
                  | ((uint32_t)__half_as_ushort(__float2half(y01)) << 16);
                *(uint32_t*)(Ch + o1) =
                    (uint32_t)__half_as_ushort(__float2half(y10))
                  | ((uint32_t)__half_as_ushort(__float2half(y11)) << 16);
            }
        }
    }
}

// ---------------------------------------------------------------------------
extern "C" void kernel_launch(void* const* d_in, const int* in_sizes, int n_in,
                              void* d_out, int out_size)
{
    (void)in_sizes; (void)n_in; (void)out_size;
    const float* x  = (const float*)d_in[0];
    const float* w1 = (const float*)d_in[1];
    const float* b1 = (const float*)d_in[2];
    const float* w2 = (const float*)d_in[3];
    const float* b2 = (const float*)d_in[4];
    const float* g1w[2] = { (const float*)d_in[5],  (const float*)d_in[9]  };
    const float* g1b[2] = { (const float*)d_in[6],  (const float*)d_in[10] };
    const float* g2w[2] = { (const float*)d_in[7],  (const float*)d_in[11] };
    const float* g2b[2] = { (const float*)d_in[8],  (const float*)d_in[12] };
    float* out = (float*)d_out;

    __half *wh, *aA, *aB;
    cudaGetSymbolAddress((void**)&wh, g_wh);
    cudaGetSymbolAddress((void**)&aA, g_aA);
    cudaGetSymbolAddress((void**)&aB, g_aB);

    const size_t OW1 = 0, OW2 = 8388608;
    const size_t OG[4] = { 16777216, 50331648, 83886080, 117440512 };

    cudaFuncSetAttribute(gemm1p, cudaFuncAttributeMaxDynamicSharedMemorySize, SMEM_SZ);

    auto conv = [&](const float* src, __half* dst, size_t n) {
        int n4 = (int)(n / 4);
        conv_h<<<(n4 + 255) / 256, 256>>>((const float4*)src, dst, n4);
    };
    conv(x,      aB,         (size_t)T_TOK * HID);
    conv(w1,     wh + OW1,   (size_t)IMM * HID);
    conv(w2,     wh + OW2,   (size_t)HID * IMM);
    conv(g1w[0], wh + OG[0], (size_t)4 * IMM * HID);
    conv(g2w[0], wh + OG[1], (size_t)4 * HID * IMM);
    conv(g1w[1], wh + OG[2], (size_t)4 * IMM * HID);
    conv(g2w[1], wh + OG[3], (size_t)4 * HID * IMM);

    const int Mg = T_TOK / 4;
    dim3 blk(256);

    // 1) x @ w1^T -> actA  [16384, 4096]
    gemm1p<<<dim3(IMM / BN, T_TOK / BM, 1), blk, SMEM_SZ>>>(
        aB, wh + OW1, b1, nullptr, aA, T_TOK, IMM, HID, 0);
    // 2) actA @ w2^T -> actB  [16384, 2048]
    gemm1p<<<dim3(HID / BN, T_TOK / BM, 1), blk, SMEM_SZ>>>(
        aA, wh + OW2, b2, nullptr, aB, T_TOK, HID, IMM, 0);
    // 3..6) two grouped-MLP layers
    for (int li = 0; li < 2; li++) {
        gemm1p<<<dim3(IMM / BN, Mg / BM, 4), blk, SMEM_SZ>>>(
            aB, wh + OG[2 * li], g1b[li], nullptr, aA, Mg, IMM, HID, 0);
        int fin = (li == 1);
        gemm1p<<<dim3(HID / BN, Mg / BM, 4), blk, SMEM_SZ>>>(
            aA, wh + OG[2 * li + 1], g2b[li],
            fin ? out : nullptr, aB, Mg, HID, IMM, fin);
    }
}